// round 5
// baseline (speedup 1.0000x reference)
#include <cuda_runtime.h>
#include <math.h>

// Problem constants
#define B_   32
#define N_   4096
#define D_   256
#define S_   16
#define K_   8
#define H_   128
#define LN_EPS 1e-5f
#define EPS_ 1e-8f
#define SCALE_ 0.25f

// ---------------- device scratch ----------------
__device__ __align__(16) float g_wt[D_ * 32];   // wt[d][c], c<16: wk*lnw, c>=16: wv*lnw
__device__ float g_c1[32];
__device__ float g_c2[32];
__device__ __align__(16) float g_kv[(long long)B_ * N_ * 32];  // [b][n][k0..15|v0..15]
__device__ float g_q[B_ * K_ * S_];
__device__ float g_num[B_ * K_ * S_];
__device__ float g_den[B_ * K_];
__device__ float g_slots[B_ * K_ * S_];

// ---------------- f32x2 helpers ----------------
__device__ __forceinline__ unsigned long long pack2(float lo, float hi) {
    unsigned long long r;
    asm("mov.b64 %0, {%1, %2};" : "=l"(r) : "f"(lo), "f"(hi));
    return r;
}
__device__ __forceinline__ void unpack2(unsigned long long v, float& lo, float& hi) {
    asm("mov.b64 {%0, %1}, %2;" : "=f"(lo), "=f"(hi) : "l"(v));
}
__device__ __forceinline__ void fma2(unsigned long long& d, unsigned long long a, unsigned long long b) {
    asm("fma.rn.f32x2 %0, %1, %2, %0;" : "+l"(d) : "l"(a), "l"(b));
}

// ---------------- prep: weights transpose + c1/c2 + slots copy (parallel) ----------------
__global__ void __launch_bounds__(1024) prep_kernel(
    const float* __restrict__ wk, const float* __restrict__ wv,
    const float* __restrict__ ln_w, const float* __restrict__ ln_b,
    const float* __restrict__ init_slots) {
    const int t = threadIdx.x;  // 1024
    // weight transpose + ln_w fold: 8192 entries
#pragma unroll
    for (int i = 0; i < 8; i++) {
        int idx = t + i * 1024;
        int c = idx & 31, d = idx >> 5;
        float w = (c < 16) ? wk[c * D_ + d] : wv[(c - 16) * D_ + d];
        g_wt[d * 32 + c] = w * ln_w[d];
    }
    // c1/c2: one warp per output column
    {
        int w = t >> 5, l = t & 31;      // warp 0..31 -> col
        const float* wr = (w < 16) ? &wk[w * D_] : &wv[(w - 16) * D_];
        float c1 = 0.f, c2 = 0.f;
#pragma unroll
        for (int j = 0; j < 8; j++) {
            int d = l + j * 32;
            float wv_ = wr[d];
            c1 = fmaf(wv_, ln_w[d], c1);
            c2 = fmaf(wv_, ln_b[d], c2);
        }
#pragma unroll
        for (int o = 16; o >= 1; o >>= 1) {
            c1 += __shfl_xor_sync(0xffffffffu, c1, o);
            c2 += __shfl_xor_sync(0xffffffffu, c2, o);
        }
        if (l == 0) {
            g_c1[w] = c1;
            g_c2[w] = c2;
        }
    }
    // slots copy
#pragma unroll
    for (int i = 0; i < 4; i++) g_slots[t + i * 1024] = init_slots[t + i * 1024];
}

// ---------------- fused LayerNorm + k/v projection (R3 verbatim) ----------------
#define LP_ROWS 64
#define LP_THREADS 128
#define LP_XS_PITCH 257
#define LP_SMEM_FLOATS (LP_ROWS * LP_XS_PITCH + D_ * 32 + 2 * LP_ROWS)

__global__ void __launch_bounds__(LP_THREADS) lnproj_kernel(const float* __restrict__ in) {
    extern __shared__ float sm[];
    float* xs = sm;                               // [64][257] (scalar access only)
    float* wt = sm + LP_ROWS * LP_XS_PITCH;       // [256][32]; byte offset 65792 (16B aligned)
    float* mu_s = wt + D_ * 32;
    float* rs_s = mu_s + LP_ROWS;

    const int t = threadIdx.x;
    const long long row0 = (long long)blockIdx.x * LP_ROWS;

    // stage weights (g_wt is 16B aligned)
    {
        const float4* src = (const float4*)g_wt;
        float4* dst = (float4*)wt;
#pragma unroll
        for (int i = 0; i < 16; i++) dst[t + i * LP_THREADS] = src[t + i * LP_THREADS];
    }
    // stage inputs: SCALAR, warp reads 128B coalesced
    {
        const float* src = in + row0 * D_;
#pragma unroll 8
        for (int i = 0; i < 128; i++) {
            int idx = t + i * LP_THREADS;   // 0..16383
            int r = idx >> 8, c = idx & 255;
            xs[r * LP_XS_PITCH + c] = src[idx];
        }
    }
    __syncthreads();

    // LN stats: 2 threads / row
    {
        int r = t >> 1, half = t & 1;
        const float* xr = &xs[r * LP_XS_PITCH + half * 128];
        float s = 0.f, ss = 0.f;
#pragma unroll 8
        for (int j = 0; j < 128; j++) {
            float x = xr[j];
            s += x;
            ss = fmaf(x, x, ss);
        }
        s += __shfl_xor_sync(0xffffffffu, s, 1);
        ss += __shfl_xor_sync(0xffffffffu, ss, 1);
        if (half == 0) {
            float mu = s * (1.f / 256.f);
            float var = ss * (1.f / 256.f) - mu * mu;
            mu_s[r] = mu;
            rs_s[r] = rsqrtf(var + LN_EPS);
        }
    }
    __syncthreads();

    // GEMM: thread = rows {rr, rr+32} x cols [c0, c0+8)
    const int rr = t & 31;
    const int c0 = (t >> 5) * 8;
    unsigned long long acc[2][4];
#pragma unroll
    for (int p = 0; p < 2; p++)
#pragma unroll
        for (int c = 0; c < 4; c++) acc[p][c] = 0ull;

    const float* xa_p = &xs[rr * LP_XS_PITCH];
    const float* xb_p = &xs[(rr + 32) * LP_XS_PITCH];
#pragma unroll 8
    for (int d = 0; d < D_; d++) {
        float xa = xa_p[d];
        float xb = xb_p[d];
        unsigned long long xa2 = pack2(xa, xa);
        unsigned long long xb2 = pack2(xb, xb);
        ulonglong2 w01 = *(const ulonglong2*)&wt[d * 32 + c0];
        ulonglong2 w23 = *(const ulonglong2*)&wt[d * 32 + c0 + 4];
        fma2(acc[0][0], xa2, w01.x);
        fma2(acc[0][1], xa2, w01.y);
        fma2(acc[0][2], xa2, w23.x);
        fma2(acc[0][3], xa2, w23.y);
        fma2(acc[1][0], xb2, w01.x);
        fma2(acc[1][1], xb2, w01.y);
        fma2(acc[1][2], xb2, w23.x);
        fma2(acc[1][3], xb2, w23.y);
    }

    // epilogue: out = rs*(acc - mu*c1) + c2
    float c1v[8], c2v[8];
#pragma unroll
    for (int j = 0; j < 8; j++) {
        c1v[j] = g_c1[c0 + j];
        c2v[j] = g_c2[c0 + j];
    }
#pragma unroll
    for (int p = 0; p < 2; p++) {
        int r = rr + 32 * p;
        float mu = mu_s[r], rs = rs_s[r];
        float o[8];
#pragma unroll
        for (int c = 0; c < 4; c++) {
            float lo, hi;
            unpack2(acc[p][c], lo, hi);
            o[2 * c] = fmaf(rs, lo - mu * c1v[2 * c], c2v[2 * c]);
            o[2 * c + 1] = fmaf(rs, hi - mu * c1v[2 * c + 1], c2v[2 * c + 1]);
        }
        float4* dst = (float4*)&g_kv[(row0 + r) * 32 + c0];
        dst[0] = make_float4(o[0], o[1], o[2], o[3]);
        dst[1] = make_float4(o[4], o[5], o[6], o[7]);
    }
}

// ---------------- per-iteration q-prep (R3 verbatim) ----------------
__global__ void qprep_kernel(const float* __restrict__ ln_s_w, const float* __restrict__ ln_s_b,
                             const float* __restrict__ wq) {
    int t = threadIdx.x;  // 256 threads, one per (b,k)
    g_den[t] = 0.f;
#pragma unroll
    for (int j = 0; j < 16; j++) g_num[t * 16 + j] = 0.f;

    float x[S_];
    float s = 0.f;
#pragma unroll
    for (int j = 0; j < S_; j++) {
        x[j] = g_slots[t * S_ + j];
        s += x[j];
    }
    float mu = s * (1.f / 16.f);
    float ss = 0.f;
#pragma unroll
    for (int j = 0; j < S_; j++) {
        float d = x[j] - mu;
        ss = fmaf(d, d, ss);
    }
    float rs = rsqrtf(ss * (1.f / 16.f) + LN_EPS);
    float y[S_];
#pragma unroll
    for (int j = 0; j < S_; j++) y[j] = (x[j] - mu) * rs * ln_s_w[j] + ln_s_b[j];
#pragma unroll
    for (int tt = 0; tt < S_; tt++) {
        float q = 0.f;
#pragma unroll
        for (int j = 0; j < S_; j++) q = fmaf(y[j], wq[tt * S_ + j], q);
        g_q[t * S_ + tt] = q;
    }
}

// ---------------- attention (R3 body, one tile per block) ----------------
#define AT_TILE 128
#define AT_KV_PITCH 36

__global__ void __launch_bounds__(128) attn_kernel(float* __restrict__ out_attn, int write_attn) {
    __shared__ float q_s[K_ * S_];
    __shared__ float kvs[AT_TILE * AT_KV_PITCH];
    __shared__ float red[128 * 17];
    __shared__ float a_s[K_ * (AT_TILE + 4)];

    const int b = blockIdx.y;
    const int t = threadIdx.x;
    const int k = t & 7;
    const int g = t >> 3;  // 0..15

    q_s[t] = g_q[b * 128 + t];

    float num[S_];
#pragma unroll
    for (int s = 0; s < S_; s++) num[s] = 0.f;
    float den = 0.f;

    __syncthreads();
    float qr[S_];
#pragma unroll
    for (int s = 0; s < S_; s++) qr[s] = q_s[k * S_ + s];

    const int n0 = blockIdx.x * AT_TILE;
    {
        __syncthreads();
        // stage kv tile: 128 rows x 32 floats (pitch 36 floats = 144B, 16B aligned)
        {
            const float4* src = (const float4*)(g_kv + ((long long)b * N_ + n0) * 32);
#pragma unroll
            for (int i = 0; i < 8; i++) {
                int idx = t + i * 128;
                int r = idx >> 3, f = idx & 7;
                *(float4*)&kvs[r * AT_KV_PITCH + 4 * f] = src[idx];
            }
        }
        __syncthreads();

#pragma unroll 2
        for (int j = 0; j < AT_TILE / 16; j++) {
            int nl = g + 16 * j;
            const float* kn = &kvs[nl * AT_KV_PITCH];
            float logit = 0.f;
#pragma unroll
            for (int s = 0; s < S_; s++) logit = fmaf(qr[s], kn[s], logit);
            logit *= SCALE_;
            float m = logit;
            m = fmaxf(m, __shfl_xor_sync(0xffffffffu, m, 1));
            m = fmaxf(m, __shfl_xor_sync(0xffffffffu, m, 2));
            m = fmaxf(m, __shfl_xor_sync(0xffffffffu, m, 4));
            float e = __expf(logit - m);
            float sum = e;
            sum += __shfl_xor_sync(0xffffffffu, sum, 1);
            sum += __shfl_xor_sync(0xffffffffu, sum, 2);
            sum += __shfl_xor_sync(0xffffffffu, sum, 4);
            float a = e / sum + EPS_;
            if (write_attn) a_s[k * (AT_TILE + 4) + nl] = a;
            den += a;
            const float* vn = kn + 16;
#pragma unroll
            for (int s = 0; s < S_; s++) num[s] = fmaf(a, vn[s], num[s]);
        }

        if (write_attn) {
            __syncthreads();
            float* dst = out_attn + (long long)b * K_ * N_ + n0;
#pragma unroll
            for (int i = 0; i < 8; i++) {
                int idx = t + i * 128;
                int kk = idx >> 7, nn = idx & 127;
                dst[(long long)kk * N_ + nn] = a_s[kk * (AT_TILE + 4) + nn];
            }
        }
    }

    // block reduction: red[(g*8+k)*17 + s]  (R3 verbatim)
    __syncthreads();
#pragma unroll
    for (int s = 0; s < S_; s++) red[t * 17 + s] = num[s];
    red[t * 17 + 16] = den;
    __syncthreads();
    {
        int k2 = t >> 4, s2 = t & 15;
        float v = 0.f;
#pragma unroll
        for (int gg = 0; gg < 16; gg++) v += red[(gg * 8 + k2) * 17 + s2];
        atomicAdd(&g_num[(b * K_ + k2) * S_ + s2], v);
        if (s2 == 0) {
            float dv = 0.f;
#pragma unroll
            for (int gg = 0; gg < 16; gg++) dv += red[(gg * 8 + k2) * 17 + 16];
            atomicAdd(&g_den[b * K_ + k2], dv);
        }
    }
}

// ---------------- GRU + LayerNorm + MLP (R3 verbatim) ----------------
__global__ void __launch_bounds__(128) update_kernel(
    const float* __restrict__ w_ih, const float* __restrict__ w_hh,
    const float* __restrict__ b_ih, const float* __restrict__ b_hh,
    const float* __restrict__ ln_m_w, const float* __restrict__ ln_m_b,
    const float* __restrict__ w1, const float* __restrict__ b1,
    const float* __restrict__ w2, const float* __restrict__ b2,
    float* __restrict__ out_slots, int write_out) {
    __shared__ float upd[128], sp[128], gi_s[K_ * 48], gh_s[K_ * 48];
    __shared__ float h_s[128], y_s[128], hid[K_ * H_];
    __shared__ float ws_ih[768], ws_hh[768], ws1[H_ * S_], ws2[S_ * H_];
    __shared__ float bs_ih[48], bs_hh[48], bs1[H_], bs2[S_], lnw[S_], lnb[S_];

    const int b = blockIdx.x;
    const int t = threadIdx.x;  // 128

    for (int i = t; i < 768; i += 128) {
        ws_ih[i] = w_ih[i];
        ws_hh[i] = w_hh[i];
    }
    for (int i = t; i < H_ * S_; i += 128) {
        ws1[i] = w1[i];
        ws2[i] = w2[i];
    }
    if (t < 48) {
        bs_ih[t] = b_ih[t];
        bs_hh[t] = b_hh[t];
    }
    bs1[t] = b1[t];
    if (t < 16) {
        bs2[t] = b2[t];
        lnw[t] = ln_m_w[t];
        lnb[t] = ln_m_b[t];
    }
    upd[t] = g_num[b * 128 + t] / g_den[b * K_ + (t >> 4)];
    sp[t] = g_slots[b * 128 + t];
    __syncthreads();

#pragma unroll
    for (int i = 0; i < 3; i++) {
        int idx = t + i * 128;
        int kk = idx / 48, j = idx % 48;
        float gi = bs_ih[j], gh = bs_hh[j];
#pragma unroll
        for (int s = 0; s < S_; s++) {
            gi = fmaf(upd[kk * S_ + s], ws_ih[j * S_ + s], gi);
            gh = fmaf(sp[kk * S_ + s], ws_hh[j * S_ + s], gh);
        }
        gi_s[idx] = gi;
        gh_s[idx] = gh;
    }
    __syncthreads();
    {
        int kk = t >> 4, s = t & 15;
        float ir = gi_s[kk * 48 + s], hr = gh_s[kk * 48 + s];
        float iz = gi_s[kk * 48 + 16 + s], hz = gh_s[kk * 48 + 16 + s];
        float inn = gi_s[kk * 48 + 32 + s], hn = gh_s[kk * 48 + 32 + s];
        float r = 1.f / (1.f + __expf(-(ir + hr)));
        float z = 1.f / (1.f + __expf(-(iz + hz)));
        float n = tanhf(inn + r * hn);
        float h = (1.f - z) * n + z * sp[t];
        h_s[t] = h;
        float s1 = h, s2 = h * h;
#pragma unroll
        for (int o = 1; o <= 8; o <<= 1) {
            s1 += __shfl_xor_sync(0xffffffffu, s1, o);
            s2 += __shfl_xor_sync(0xffffffffu, s2, o);
        }
        float mu = s1 * (1.f / 16.f);
        float var = s2 * (1.f / 16.f) - mu * mu;
        float rs = rsqrtf(var + LN_EPS);
        y_s[t] = (h - mu) * rs * lnw[s] + lnb[s];
    }
    __syncthreads();
#pragma unroll
    for (int i = 0; i < 8; i++) {
        int idx = t + i * 128;
        int kk = idx >> 7, hh = idx & 127;
        float acc = bs1[hh];
#pragma unroll
        for (int s = 0; s < S_; s++) acc = fmaf(y_s[kk * S_ + s], ws1[hh * S_ + s], acc);
        hid[idx] = fmaxf(acc, 0.f);
    }
    __syncthreads();
    {
        int kk = t >> 4, s = t & 15;
        float acc = bs2[s];
#pragma unroll 8
        for (int h = 0; h < H_; h++) acc = fmaf(hid[kk * H_ + h], ws2[s * H_ + h], acc);
        float res = h_s[t] + acc;
        g_slots[b * 128 + t] = res;
        if (write_out) out_slots[b * 128 + t] = res;
    }
}

// ---------------- final attn normalization (R3 verbatim) ----------------
__global__ void attn_norm_kernel(float* __restrict__ attn) {
    long long i = (long long)blockIdx.x * blockDim.x + threadIdx.x;
    int bk = (int)(i >> 12);
    attn[i] = attn[i] / g_den[bk];
}

// ---------------- launch ----------------
extern "C" void kernel_launch(void* const* d_in, const int* in_sizes, int n_in,
                              void* d_out, int out_size) {
    const float* inputs = (const float*)d_in[0];
    const float* init_slots = (const float*)d_in[1];
    const float* ln_in_w = (const float*)d_in[2];
    const float* ln_in_b = (const float*)d_in[3];
    const float* ln_s_w = (const float*)d_in[4];
    const float* ln_s_b = (const float*)d_in[5];
    const float* ln_m_w = (const float*)d_in[6];
    const float* ln_m_b = (const float*)d_in[7];
    const float* wq = (const float*)d_in[8];
    const float* wk = (const float*)d_in[9];
    const float* wv = (const float*)d_in[10];
    const float* w_ih = (const float*)d_in[11];
    const float* w_hh = (const float*)d_in[12];
    const float* b_ih = (const float*)d_in[13];
    const float* b_hh = (const float*)d_in[14];
    const float* mlp_w1 = (const float*)d_in[15];
    const float* mlp_b1 = (const float*)d_in[16];
    const float* mlp_w2 = (const float*)d_in[17];
    const float* mlp_b2 = (const float*)d_in[18];

    float* out_slots = (float*)d_out;
    float* out_attn = out_slots + B_ * K_ * S_;

    const int lp_smem = LP_SMEM_FLOATS * sizeof(float);
    cudaFuncSetAttribute(lnproj_kernel, cudaFuncAttributeMaxDynamicSharedMemorySize, lp_smem);

    prep_kernel<<<1, 1024>>>(wk, wv, ln_in_w, ln_in_b, init_slots);
    lnproj_kernel<<<(B_ * N_) / LP_ROWS, LP_THREADS, lp_smem>>>(inputs);
    for (int it = 0; it < 3; it++) {
        qprep_kernel<<<1, 256>>>(ln_s_w, ln_s_b, wq);
        attn_kernel<<<dim3(N_ / AT_TILE, B_), 128>>>(out_attn, it == 2);
        update_kernel<<<B_, 128>>>(w_ih, w_hh, b_ih, b_hh, ln_m_w, ln_m_b,
                                   mlp_w1, mlp_b1, mlp_w2, mlp_b2, out_slots, it == 2);
    }
    attn_norm_kernel<<<(B_ * K_ * N_) / 256, 256>>>(out_attn);
}

// round 7
// speedup vs baseline: 1.0443x; 1.0443x over previous
#include <cuda_runtime.h>
#include <math.h>

// Problem constants
#define B_   32
#define N_   4096
#define D_   256
#define S_   16
#define K_   8
#define H_   128
#define LN_EPS 1e-5f
#define EPS_ 1e-8f
#define SCALE_ 0.25f

// ---------------- device scratch ----------------
__device__ __align__(16) float g_wt[D_ * 32];   // wt[d][c], c<16: wk*lnw, c>=16: wv*lnw
__device__ float g_c1[32];
__device__ float g_c2[32];
__device__ __align__(16) float g_kv[(long long)B_ * N_ * 32];  // [b][n][k0..15|v0..15]
__device__ float g_q[B_ * K_ * S_];
__device__ float g_num[B_ * K_ * S_];
__device__ float g_den[B_ * K_];
__device__ float g_slots[B_ * K_ * S_];

// ---------------- f32x2 helpers ----------------
__device__ __forceinline__ unsigned long long pack2(float lo, float hi) {
    unsigned long long r;
    asm("mov.b64 %0, {%1, %2};" : "=l"(r) : "f"(lo), "f"(hi));
    return r;
}
__device__ __forceinline__ void unpack2(unsigned long long v, float& lo, float& hi) {
    asm("mov.b64 {%0, %1}, %2;" : "=f"(lo), "=f"(hi) : "l"(v));
}
__device__ __forceinline__ void fma2(unsigned long long& d, unsigned long long a, unsigned long long b) {
    asm("fma.rn.f32x2 %0, %1, %2, %0;" : "+l"(d) : "l"(a), "l"(b));
}

// ---------------- prep: weights transpose + c1/c2 + slots copy (R5-pass verbatim) ----------------
__global__ void __launch_bounds__(1024) prep_kernel(
    const float* __restrict__ wk, const float* __restrict__ wv,
    const float* __restrict__ ln_w, const float* __restrict__ ln_b,
    const float* __restrict__ init_slots) {
    const int t = threadIdx.x;  // 1024
#pragma unroll
    for (int i = 0; i < 8; i++) {
        int idx = t + i * 1024;
        int c = idx & 31, d = idx >> 5;
        float w = (c < 16) ? wk[c * D_ + d] : wv[(c - 16) * D_ + d];
        g_wt[d * 32 + c] = w * ln_w[d];
    }
    {
        int w = t >> 5, l = t & 31;
        const float* wr = (w < 16) ? &wk[w * D_] : &wv[(w - 16) * D_];
        float c1 = 0.f, c2 = 0.f;
#pragma unroll
        for (int j = 0; j < 8; j++) {
            int d = l + j * 32;
            float wv_ = wr[d];
            c1 = fmaf(wv_, ln_w[d], c1);
            c2 = fmaf(wv_, ln_b[d], c2);
        }
#pragma unroll
        for (int o = 16; o >= 1; o >>= 1) {
            c1 += __shfl_xor_sync(0xffffffffu, c1, o);
            c2 += __shfl_xor_sync(0xffffffffu, c2, o);
        }
        if (l == 0) {
            g_c1[w] = c1;
            g_c2[w] = c2;
        }
    }
#pragma unroll
    for (int i = 0; i < 4; i++) g_slots[t + i * 1024] = init_slots[t + i * 1024];
}

// ---------------- fused LayerNorm + k/v projection (R5-pass verbatim) ----------------
#define LP_ROWS 64
#define LP_THREADS 128
#define LP_XS_PITCH 257
#define LP_SMEM_FLOATS (LP_ROWS * LP_XS_PITCH + D_ * 32 + 2 * LP_ROWS)

__global__ void __launch_bounds__(LP_THREADS) lnproj_kernel(const float* __restrict__ in) {
    extern __shared__ float sm[];
    float* xs = sm;                               // [64][257] scalar access
    float* wt = sm + LP_ROWS * LP_XS_PITCH;       // [256][32]
    float* mu_s = wt + D_ * 32;
    float* rs_s = mu_s + LP_ROWS;

    const int t = threadIdx.x;
    const long long row0 = (long long)blockIdx.x * LP_ROWS;

    {
        const float4* src = (const float4*)g_wt;
        float4* dst = (float4*)wt;
#pragma unroll
        for (int i = 0; i < 16; i++) dst[t + i * LP_THREADS] = src[t + i * LP_THREADS];
    }
    {
        const float* src = in + row0 * D_;
#pragma unroll 8
        for (int i = 0; i < 128; i++) {
            int idx = t + i * LP_THREADS;
            int r = idx >> 8, c = idx & 255;
            xs[r * LP_XS_PITCH + c] = src[idx];
        }
    }
    __syncthreads();

    {
        int r = t >> 1, half = t & 1;
        const float* xr = &xs[r * LP_XS_PITCH + half * 128];
        float s = 0.f, ss = 0.f;
#pragma unroll 8
        for (int j = 0; j < 128; j++) {
            float x = xr[j];
            s += x;
            ss = fmaf(x, x, ss);
        }
        s += __shfl_xor_sync(0xffffffffu, s, 1);
        ss += __shfl_xor_sync(0xffffffffu, ss, 1);
        if (half == 0) {
            float mu = s * (1.f / 256.f);
            float var = ss * (1.f / 256.f) - mu * mu;
            mu_s[r] = mu;
            rs_s[r] = rsqrtf(var + LN_EPS);
        }
    }
    __syncthreads();

    const int rr = t & 31;
    const int c0 = (t >> 5) * 8;
    unsigned long long acc[2][4];
#pragma unroll
    for (int p = 0; p < 2; p++)
#pragma unroll
        for (int c = 0; c < 4; c++) acc[p][c] = 0ull;

    const float* xa_p = &xs[rr * LP_XS_PITCH];
    const float* xb_p = &xs[(rr + 32) * LP_XS_PITCH];
#pragma unroll 8
    for (int d = 0; d < D_; d++) {
        float xa = xa_p[d];
        float xb = xb_p[d];
        unsigned long long xa2 = pack2(xa, xa);
        unsigned long long xb2 = pack2(xb, xb);
        ulonglong2 w01 = *(const ulonglong2*)&wt[d * 32 + c0];
        ulonglong2 w23 = *(const ulonglong2*)&wt[d * 32 + c0 + 4];
        fma2(acc[0][0], xa2, w01.x);
        fma2(acc[0][1], xa2, w01.y);
        fma2(acc[0][2], xa2, w23.x);
        fma2(acc[0][3], xa2, w23.y);
        fma2(acc[1][0], xb2, w01.x);
        fma2(acc[1][1], xb2, w01.y);
        fma2(acc[1][2], xb2, w23.x);
        fma2(acc[1][3], xb2, w23.y);
    }

    float c1v[8], c2v[8];
#pragma unroll
    for (int j = 0; j < 8; j++) {
        c1v[j] = g_c1[c0 + j];
        c2v[j] = g_c2[c0 + j];
    }
#pragma unroll
    for (int p = 0; p < 2; p++) {
        int r = rr + 32 * p;
        float mu = mu_s[r], rs = rs_s[r];
        float o[8];
#pragma unroll
        for (int c = 0; c < 4; c++) {
            float lo, hi;
            unpack2(acc[p][c], lo, hi);
            o[2 * c] = fmaf(rs, lo - mu * c1v[2 * c], c2v[2 * c]);
            o[2 * c + 1] = fmaf(rs, hi - mu * c1v[2 * c + 1], c2v[2 * c + 1]);
        }
        float4* dst = (float4*)&g_kv[(row0 + r) * 32 + c0];
        dst[0] = make_float4(o[0], o[1], o[2], o[3]);
        dst[1] = make_float4(o[4], o[5], o[6], o[7]);
    }
}

// ---------------- q-prep (R5-pass verbatim; launched ONCE before the loop) ----------------
__global__ void qprep_kernel(const float* __restrict__ ln_s_w, const float* __restrict__ ln_s_b,
                             const float* __restrict__ wq) {
    int t = threadIdx.x;  // 256 threads, one per (b,k)
    g_den[t] = 0.f;
#pragma unroll
    for (int j = 0; j < 16; j++) g_num[t * 16 + j] = 0.f;

    float x[S_];
    float s = 0.f;
#pragma unroll
    for (int j = 0; j < S_; j++) {
        x[j] = g_slots[t * S_ + j];
        s += x[j];
    }
    float mu = s * (1.f / 16.f);
    float ss = 0.f;
#pragma unroll
    for (int j = 0; j < S_; j++) {
        float d = x[j] - mu;
        ss = fmaf(d, d, ss);
    }
    float rs = rsqrtf(ss * (1.f / 16.f) + LN_EPS);
    float y[S_];
#pragma unroll
    for (int j = 0; j < S_; j++) y[j] = (x[j] - mu) * rs * ln_s_w[j] + ln_s_b[j];
#pragma unroll
    for (int tt = 0; tt < S_; tt++) {
        float q = 0.f;
#pragma unroll
        for (int j = 0; j < S_; j++) q = fmaf(y[j], wq[tt * S_ + j], q);
        g_q[t * S_ + tt] = q;
    }
}

// ---------------- attention (R5-pass verbatim) ----------------
#define AT_TILE 128
#define AT_KV_PITCH 36

__global__ void __launch_bounds__(128) attn_kernel(float* __restrict__ out_attn, int write_attn) {
    __shared__ float q_s[K_ * S_];
    __shared__ float kvs[AT_TILE * AT_KV_PITCH];
    __shared__ float red[128 * 17];
    __shared__ float a_s[K_ * (AT_TILE + 4)];

    const int b = blockIdx.y;
    const int t = threadIdx.x;
    const int k = t & 7;
    const int g = t >> 3;  // 0..15

    q_s[t] = g_q[b * 128 + t];

    float num[S_];
#pragma unroll
    for (int s = 0; s < S_; s++) num[s] = 0.f;
    float den = 0.f;

    __syncthreads();
    float qr[S_];
#pragma unroll
    for (int s = 0; s < S_; s++) qr[s] = q_s[k * S_ + s];

    const int n0 = blockIdx.x * AT_TILE;
    {
        __syncthreads();
        {
            const float4* src = (const float4*)(g_kv + ((long long)b * N_ + n0) * 32);
#pragma unroll
            for (int i = 0; i < 8; i++) {
                int idx = t + i * 128;
                int r = idx >> 3, f = idx & 7;
                *(float4*)&kvs[r * AT_KV_PITCH + 4 * f] = src[idx];
            }
        }
        __syncthreads();

#pragma unroll 2
        for (int j = 0; j < AT_TILE / 16; j++) {
            int nl = g + 16 * j;
            const float* kn = &kvs[nl * AT_KV_PITCH];
            float logit = 0.f;
#pragma unroll
            for (int s = 0; s < S_; s++) logit = fmaf(qr[s], kn[s], logit);
            logit *= SCALE_;
            float m = logit;
            m = fmaxf(m, __shfl_xor_sync(0xffffffffu, m, 1));
            m = fmaxf(m, __shfl_xor_sync(0xffffffffu, m, 2));
            m = fmaxf(m, __shfl_xor_sync(0xffffffffu, m, 4));
            float e = __expf(logit - m);
            float sum = e;
            sum += __shfl_xor_sync(0xffffffffu, sum, 1);
            sum += __shfl_xor_sync(0xffffffffu, sum, 2);
            sum += __shfl_xor_sync(0xffffffffu, sum, 4);
            float a = e / sum + EPS_;
            if (write_attn) a_s[k * (AT_TILE + 4) + nl] = a;
            den += a;
            const float* vn = kn + 16;
#pragma unroll
            for (int s = 0; s < S_; s++) num[s] = fmaf(a, vn[s], num[s]);
        }

        if (write_attn) {
            __syncthreads();
            float* dst = out_attn + (long long)b * K_ * N_ + n0;
#pragma unroll
            for (int i = 0; i < 8; i++) {
                int idx = t + i * 128;
                int kk = idx >> 7, nn = idx & 127;
                dst[(long long)kk * N_ + nn] = a_s[kk * (AT_TILE + 4) + nn];
            }
        }
    }

    __syncthreads();
#pragma unroll
    for (int s = 0; s < S_; s++) red[t * 17 + s] = num[s];
    red[t * 17 + 16] = den;
    __syncthreads();
    {
        int k2 = t >> 4, s2 = t & 15;
        float v = 0.f;
#pragma unroll
        for (int gg = 0; gg < 16; gg++) v += red[(gg * 8 + k2) * 17 + s2];
        atomicAdd(&g_num[(b * K_ + k2) * S_ + s2], v);
        if (s2 == 0) {
            float dv = 0.f;
#pragma unroll
            for (int gg = 0; gg < 16; gg++) dv += red[(gg * 8 + k2) * 17 + 16];
            atomicAdd(&g_den[b * K_ + k2], dv);
        }
    }
}

// ---------------- GRU + LayerNorm + MLP (R5-pass body) + tail folds ----------------
__global__ void __launch_bounds__(128) update_kernel(
    const float* __restrict__ w_ih, const float* __restrict__ w_hh,
    const float* __restrict__ b_ih, const float* __restrict__ b_hh,
    const float* __restrict__ ln_m_w, const float* __restrict__ ln_m_b,
    const float* __restrict__ w1, const float* __restrict__ b1,
    const float* __restrict__ w2, const float* __restrict__ b2,
    const float* __restrict__ ln_s_w, const float* __restrict__ ln_s_b,
    const float* __restrict__ wq,
    float* __restrict__ out_slots, float* __restrict__ out_attn, int write_out) {
    __shared__ float upd[128], sp[128], gi_s[K_ * 48], gh_s[K_ * 48];
    __shared__ float h_s[128], y_s[128], hid[K_ * H_];
    __shared__ float ws_ih[768], ws_hh[768], ws1[H_ * S_], ws2[S_ * H_];
    __shared__ float bs_ih[48], bs_hh[48], bs1[H_], bs2[S_], lnw[S_], lnb[S_];

    const int b = blockIdx.x;
    const int t = threadIdx.x;  // 128

    for (int i = t; i < 768; i += 128) {
        ws_ih[i] = w_ih[i];
        ws_hh[i] = w_hh[i];
    }
    for (int i = t; i < H_ * S_; i += 128) {
        ws1[i] = w1[i];
        ws2[i] = w2[i];
    }
    if (t < 48) {
        bs_ih[t] = b_ih[t];
        bs_hh[t] = b_hh[t];
    }
    bs1[t] = b1[t];
    if (t < 16) {
        bs2[t] = b2[t];
        lnw[t] = ln_m_w[t];
        lnb[t] = ln_m_b[t];
    }
    upd[t] = g_num[b * 128 + t] / g_den[b * K_ + (t >> 4)];
    sp[t] = g_slots[b * 128 + t];
    __syncthreads();

#pragma unroll
    for (int i = 0; i < 3; i++) {
        int idx = t + i * 128;
        int kk = idx / 48, j = idx % 48;
        float gi = bs_ih[j], gh = bs_hh[j];
#pragma unroll
        for (int s = 0; s < S_; s++) {
            gi = fmaf(upd[kk * S_ + s], ws_ih[j * S_ + s], gi);
            gh = fmaf(sp[kk * S_ + s], ws_hh[j * S_ + s], gh);
        }
        gi_s[idx] = gi;
        gh_s[idx] = gh;
    }
    __syncthreads();
    {
        int kk = t >> 4, s = t & 15;
        float ir = gi_s[kk * 48 + s], hr = gh_s[kk * 48 + s];
        float iz = gi_s[kk * 48 + 16 + s], hz = gh_s[kk * 48 + 16 + s];
        float inn = gi_s[kk * 48 + 32 + s], hn = gh_s[kk * 48 + 32 + s];
        float r = 1.f / (1.f + __expf(-(ir + hr)));
        float z = 1.f / (1.f + __expf(-(iz + hz)));
        float n = tanhf(inn + r * hn);
        float h = (1.f - z) * n + z * sp[t];
        h_s[t] = h;
        float s1 = h, s2 = h * h;
#pragma unroll
        for (int o = 1; o <= 8; o <<= 1) {
            s1 += __shfl_xor_sync(0xffffffffu, s1, o);
            s2 += __shfl_xor_sync(0xffffffffu, s2, o);
        }
        float mu = s1 * (1.f / 16.f);
        float var = s2 * (1.f / 16.f) - mu * mu;
        float rs = rsqrtf(var + LN_EPS);
        y_s[t] = (h - mu) * rs * lnw[s] + lnb[s];
    }
    __syncthreads();
#pragma unroll
    for (int i = 0; i < 8; i++) {
        int idx = t + i * 128;
        int kk = idx >> 7, hh = idx & 127;
        float acc = bs1[hh];
#pragma unroll
        for (int s = 0; s < S_; s++) acc = fmaf(y_s[kk * S_ + s], ws1[hh * S_ + s], acc);
        hid[idx] = fmaxf(acc, 0.f);
    }
    __syncthreads();
    {
        int kk = t >> 4, s = t & 15;
        float acc = bs2[s];
#pragma unroll 8
        for (int h = 0; h < H_; h++) acc = fmaf(hid[kk * H_ + h], ws2[s * H_ + h], acc);
        float res = h_s[t] + acc;
        g_slots[b * 128 + t] = res;
        if (write_out) out_slots[b * 128 + t] = res;
    }

    // ---- tail ----
    if (write_out) {
        // last iteration: normalize this batch's attn (den final; attn written by attn_kernel)
        float4* a = (float4*)(out_attn + (long long)b * K_ * N_);
        for (int i = t; i < K_ * N_ / 4; i += 128) {
            int k = i >> 10;                       // 1024 float4 per k-row
            float sc = 1.0f / g_den[b * K_ + k];
            float4 v = a[i];
            v.x *= sc;
            v.y *= sc;
            v.z *= sc;
            v.w *= sc;
            a[i] = v;
        }
    } else {
        // non-last: compute next-iteration q (verbatim qprep body, one thread per slot row)
        __syncthreads();   // make this block's g_slots writes visible to t<8 readers
        if (t < K_) {
            int r = b * K_ + t;
            float x[S_];
            float s = 0.f;
#pragma unroll
            for (int j = 0; j < S_; j++) {
                x[j] = g_slots[r * S_ + j];
                s += x[j];
            }
            float mu = s * (1.f / 16.f);
            float ss = 0.f;
#pragma unroll
            for (int j = 0; j < S_; j++) {
                float d = x[j] - mu;
                ss = fmaf(d, d, ss);
            }
            float rs = rsqrtf(ss * (1.f / 16.f) + LN_EPS);
            float y[S_];
#pragma unroll
            for (int j = 0; j < S_; j++) y[j] = (x[j] - mu) * rs * ln_s_w[j] + ln_s_b[j];
#pragma unroll
            for (int tt = 0; tt < S_; tt++) {
                float q = 0.f;
#pragma unroll
                for (int j = 0; j < S_; j++) q = fmaf(y[j], wq[tt * S_ + j], q);
                g_q[r * S_ + tt] = q;
            }
        }
        // zero accumulators for next attn pass
        g_num[b * 128 + t] = 0.f;
        if (t < K_) g_den[b * K_ + t] = 0.f;
    }
}

// ---------------- launch: 9 graph nodes ----------------
extern "C" void kernel_launch(void* const* d_in, const int* in_sizes, int n_in,
                              void* d_out, int out_size) {
    const float* inputs = (const float*)d_in[0];
    const float* init_slots = (const float*)d_in[1];
    const float* ln_in_w = (const float*)d_in[2];
    const float* ln_in_b = (const float*)d_in[3];
    const float* ln_s_w = (const float*)d_in[4];
    const float* ln_s_b = (const float*)d_in[5];
    const float* ln_m_w = (const float*)d_in[6];
    const float* ln_m_b = (const float*)d_in[7];
    const float* wq = (const float*)d_in[8];
    const float* wk = (const float*)d_in[9];
    const float* wv = (const float*)d_in[10];
    const float* w_ih = (const float*)d_in[11];
    const float* w_hh = (const float*)d_in[12];
    const float* b_ih = (const float*)d_in[13];
    const float* b_hh = (const float*)d_in[14];
    const float* mlp_w1 = (const float*)d_in[15];
    const float* mlp_b1 = (const float*)d_in[16];
    const float* mlp_w2 = (const float*)d_in[17];
    const float* mlp_b2 = (const float*)d_in[18];

    float* out_slots = (float*)d_out;
    float* out_attn = out_slots + B_ * K_ * S_;

    const int lp_smem = LP_SMEM_FLOATS * sizeof(float);
    cudaFuncSetAttribute(lnproj_kernel, cudaFuncAttributeMaxDynamicSharedMemorySize, lp_smem);

    prep_kernel<<<1, 1024>>>(wk, wv, ln_in_w, ln_in_b, init_slots);
    lnproj_kernel<<<(B_ * N_) / LP_ROWS, LP_THREADS, lp_smem>>>(inputs);
    qprep_kernel<<<1, 256>>>(ln_s_w, ln_s_b, wq);
    for (int it = 0; it < 3; it++) {
        attn_kernel<<<dim3(N_ / AT_TILE, B_), 128>>>(out_attn, it == 2);
        update_kernel<<<B_, 128>>>(w_ih, w_hh, b_ih, b_hh, ln_m_w, ln_m_b,
                                   mlp_w1, mlp_b1, mlp_w2, mlp_b2,
                                   ln_s_w, ln_s_b, wq, out_slots, out_attn, it == 2);
    }
}

// round 8
// speedup vs baseline: 1.1106x; 1.0635x over previous
#include <cuda_runtime.h>
#include <math.h>

// Problem constants
#define B_   32
#define N_   4096
#define D_   256
#define S_   16
#define K_   8
#define H_   128
#define LN_EPS 1e-5f
#define EPS_ 1e-8f
#define SCALE_ 0.25f

#define ML_GRID 512          // 32 batches x 16 groups of 256 n
#define ML_NT 256            // n per block
#define KV_PITCH 36

// ---------------- device scratch ----------------
__device__ __align__(16) float g_wt[D_ * 32];   // wt[d][c], c<16: wk*lnw, c>=16: wv*lnw
__device__ float g_c1[32];
__device__ float g_c2[32];
__device__ __align__(16) float g_kv[(long long)B_ * N_ * 32];  // [b][n][k0..15|v0..15]
__device__ float g_num3[3 * B_ * K_ * S_];      // per-iteration accumulators
__device__ float g_den3[3 * B_ * K_];
__device__ unsigned g_bar;

// ---------------- f32x2 helpers ----------------
__device__ __forceinline__ unsigned long long pack2(float lo, float hi) {
    unsigned long long r;
    asm("mov.b64 %0, {%1, %2};" : "=l"(r) : "f"(lo), "f"(hi));
    return r;
}
__device__ __forceinline__ void unpack2(unsigned long long v, float& lo, float& hi) {
    asm("mov.b64 {%0, %1}, %2;" : "=f"(lo), "=f"(hi) : "l"(v));
}
__device__ __forceinline__ void fma2(unsigned long long& d, unsigned long long a, unsigned long long b) {
    asm("fma.rn.f32x2 %0, %1, %2, %0;" : "+l"(d) : "l"(a), "l"(b));
}

// ---------------- prep: weights transpose + c1/c2 + zero acc + bar reset ----------------
__global__ void __launch_bounds__(1024) prep_kernel(
    const float* __restrict__ wk, const float* __restrict__ wv,
    const float* __restrict__ ln_w, const float* __restrict__ ln_b) {
    const int t = threadIdx.x;  // 1024
#pragma unroll
    for (int i = 0; i < 8; i++) {
        int idx = t + i * 1024;
        int c = idx & 31, d = idx >> 5;
        float w = (c < 16) ? wk[c * D_ + d] : wv[(c - 16) * D_ + d];
        g_wt[d * 32 + c] = w * ln_w[d];
    }
    {
        int w = t >> 5, l = t & 31;
        const float* wr = (w < 16) ? &wk[w * D_] : &wv[(w - 16) * D_];
        float c1 = 0.f, c2 = 0.f;
#pragma unroll
        for (int j = 0; j < 8; j++) {
            int d = l + j * 32;
            float wv_ = wr[d];
            c1 = fmaf(wv_, ln_w[d], c1);
            c2 = fmaf(wv_, ln_b[d], c2);
        }
#pragma unroll
        for (int o = 16; o >= 1; o >>= 1) {
            c1 += __shfl_xor_sync(0xffffffffu, c1, o);
            c2 += __shfl_xor_sync(0xffffffffu, c2, o);
        }
        if (l == 0) {
            g_c1[w] = c1;
            g_c2[w] = c2;
        }
    }
    // zero per-iteration accumulators + barrier
#pragma unroll
    for (int i = 0; i < 12; i++) g_num3[t + i * 1024] = 0.f;
    if (t < 768) g_den3[t] = 0.f;
    if (t == 0) g_bar = 0u;
}

// ---------------- fused LayerNorm + k/v projection (R7-pass verbatim) ----------------
#define LP_ROWS 64
#define LP_THREADS 128
#define LP_XS_PITCH 257
#define LP_SMEM_FLOATS (LP_ROWS * LP_XS_PITCH + D_ * 32 + 2 * LP_ROWS)

__global__ void __launch_bounds__(LP_THREADS) lnproj_kernel(const float* __restrict__ in) {
    extern __shared__ float sm[];
    float* xs = sm;                               // [64][257] scalar access
    float* wt = sm + LP_ROWS * LP_XS_PITCH;       // [256][32]
    float* mu_s = wt + D_ * 32;
    float* rs_s = mu_s + LP_ROWS;

    const int t = threadIdx.x;
    const long long row0 = (long long)blockIdx.x * LP_ROWS;

    {
        const float4* src = (const float4*)g_wt;
        float4* dst = (float4*)wt;
#pragma unroll
        for (int i = 0; i < 16; i++) dst[t + i * LP_THREADS] = src[t + i * LP_THREADS];
    }
    {
        const float* src = in + row0 * D_;
#pragma unroll 8
        for (int i = 0; i < 128; i++) {
            int idx = t + i * LP_THREADS;
            int r = idx >> 8, c = idx & 255;
            xs[r * LP_XS_PITCH + c] = src[idx];
        }
    }
    __syncthreads();

    {
        int r = t >> 1, half = t & 1;
        const float* xr = &xs[r * LP_XS_PITCH + half * 128];
        float s = 0.f, ss = 0.f;
#pragma unroll 8
        for (int j = 0; j < 128; j++) {
            float x = xr[j];
            s += x;
            ss = fmaf(x, x, ss);
        }
        s += __shfl_xor_sync(0xffffffffu, s, 1);
        ss += __shfl_xor_sync(0xffffffffu, ss, 1);
        if (half == 0) {
            float mu = s * (1.f / 256.f);
            float var = ss * (1.f / 256.f) - mu * mu;
            mu_s[r] = mu;
            rs_s[r] = rsqrtf(var + LN_EPS);
        }
    }
    __syncthreads();

    const int rr = t & 31;
    const int c0 = (t >> 5) * 8;
    unsigned long long acc[2][4];
#pragma unroll
    for (int p = 0; p < 2; p++)
#pragma unroll
        for (int c = 0; c < 4; c++) acc[p][c] = 0ull;

    const float* xa_p = &xs[rr * LP_XS_PITCH];
    const float* xb_p = &xs[(rr + 32) * LP_XS_PITCH];
#pragma unroll 8
    for (int d = 0; d < D_; d++) {
        float xa = xa_p[d];
        float xb = xb_p[d];
        unsigned long long xa2 = pack2(xa, xa);
        unsigned long long xb2 = pack2(xb, xb);
        ulonglong2 w01 = *(const ulonglong2*)&wt[d * 32 + c0];
        ulonglong2 w23 = *(const ulonglong2*)&wt[d * 32 + c0 + 4];
        fma2(acc[0][0], xa2, w01.x);
        fma2(acc[0][1], xa2, w01.y);
        fma2(acc[0][2], xa2, w23.x);
        fma2(acc[0][3], xa2, w23.y);
        fma2(acc[1][0], xb2, w01.x);
        fma2(acc[1][1], xb2, w01.y);
        fma2(acc[1][2], xb2, w23.x);
        fma2(acc[1][3], xb2, w23.y);
    }

    float c1v[8], c2v[8];
#pragma unroll
    for (int j = 0; j < 8; j++) {
        c1v[j] = g_c1[c0 + j];
        c2v[j] = g_c2[c0 + j];
    }
#pragma unroll
    for (int p = 0; p < 2; p++) {
        int r = rr + 32 * p;
        float mu = mu_s[r], rs = rs_s[r];
        float o[8];
#pragma unroll
        for (int c = 0; c < 4; c++) {
            float lo, hi;
            unpack2(acc[p][c], lo, hi);
            o[2 * c] = fmaf(rs, lo - mu * c1v[2 * c], c2v[2 * c]);
            o[2 * c + 1] = fmaf(rs, hi - mu * c1v[2 * c + 1], c2v[2 * c + 1]);
        }
        float4* dst = (float4*)&g_kv[(row0 + r) * 32 + c0];
        dst[0] = make_float4(o[0], o[1], o[2], o[3]);
        dst[1] = make_float4(o[4], o[5], o[6], o[7]);
    }
}

// ---------------- persistent mainloop ----------------
// smem layout (floats):
//   kvs  [0      : 9216)   256 x 36 kv tile (persistent)
//   slb  [9216   : 9344)   slots for this batch (persistent)
//   qlo  [9344   : 9472)   q for this batch (persistent); reused as inv-den on final
//   S1   [9472   : 11648)  2176: attn red [128][17]  /  upd|h|y|gi|gh|hid update scratch
//   S2   [11648  : 13728)  2080: a_s [8][260] (final iter)  /  weight staging
#define ML_SMEM_FLOATS 13728

__device__ __forceinline__ void grid_barrier(unsigned target) {
    __syncthreads();
    if (threadIdx.x == 0) {
        __threadfence();
        atomicAdd(&g_bar, 1u);
        while (*((volatile unsigned*)&g_bar) < target) {
            __nanosleep(64);
        }
        __threadfence();
    }
    __syncthreads();
}

__global__ void __launch_bounds__(128, 4) mainloop_kernel(
    const float* __restrict__ init_slots,
    const float* __restrict__ ln_s_w, const float* __restrict__ ln_s_b,
    const float* __restrict__ wq,
    const float* __restrict__ w_ih, const float* __restrict__ w_hh,
    const float* __restrict__ b_ih, const float* __restrict__ b_hh,
    const float* __restrict__ ln_m_w, const float* __restrict__ ln_m_b,
    const float* __restrict__ w1, const float* __restrict__ b1,
    const float* __restrict__ w2, const float* __restrict__ b2,
    float* __restrict__ out_slots, float* __restrict__ out_attn) {
    extern __shared__ float sm[];
    float* kvs = sm;
    float* slb = sm + 9216;
    float* qlo = sm + 9344;
    float* S1 = sm + 9472;
    float* S2 = sm + 11648;

    const int bx = blockIdx.x;
    const int b = bx >> 4;
    const int grp = bx & 15;
    const int n0 = grp * ML_NT;
    const int t = threadIdx.x;
    const int k = t & 7;
    const int g = t >> 3;

    // stage kv tile once: 256 rows x 32 floats = 2048 float4
    {
        const float4* src = (const float4*)(g_kv + ((long long)b * N_ + n0) * 32);
#pragma unroll
        for (int i = 0; i < 16; i++) {
            int idx = t + i * 128;
            int r = idx >> 3, f = idx & 7;
            *(float4*)&kvs[r * KV_PITCH + 4 * f] = src[idx];
        }
    }
    slb[t] = init_slots[b * 128 + t];
    __syncthreads();

    // initial q (proven qprep body, one thread per slot row)
    if (t < K_) {
        float x[S_];
        float s = 0.f;
#pragma unroll
        for (int j = 0; j < S_; j++) {
            x[j] = slb[t * S_ + j];
            s += x[j];
        }
        float mu = s * (1.f / 16.f);
        float ss = 0.f;
#pragma unroll
        for (int j = 0; j < S_; j++) {
            float d = x[j] - mu;
            ss = fmaf(d, d, ss);
        }
        float rs = rsqrtf(ss * (1.f / 16.f) + LN_EPS);
        float y[S_];
#pragma unroll
        for (int j = 0; j < S_; j++) y[j] = (x[j] - mu) * rs * __ldg(ln_s_w + j) + __ldg(ln_s_b + j);
#pragma unroll
        for (int tt = 0; tt < S_; tt++) {
            float q = 0.f;
#pragma unroll
            for (int j = 0; j < S_; j++) q = fmaf(y[j], __ldg(wq + tt * S_ + j), q);
            qlo[t * S_ + tt] = q;
        }
    }
    __syncthreads();

    for (int it = 0; it < 3; it++) {
        // ---------- attn phase (R7-proven inner body) ----------
        float qr[S_];
#pragma unroll
        for (int s = 0; s < S_; s++) qr[s] = qlo[k * S_ + s];
        float num[S_];
#pragma unroll
        for (int s = 0; s < S_; s++) num[s] = 0.f;
        float den = 0.f;

#pragma unroll 2
        for (int j = 0; j < ML_NT / 16; j++) {
            int nl = g + 16 * j;
            const float* kn = &kvs[nl * KV_PITCH];
            float logit = 0.f;
#pragma unroll
            for (int s = 0; s < S_; s++) logit = fmaf(qr[s], kn[s], logit);
            logit *= SCALE_;
            float m = logit;
            m = fmaxf(m, __shfl_xor_sync(0xffffffffu, m, 1));
            m = fmaxf(m, __shfl_xor_sync(0xffffffffu, m, 2));
            m = fmaxf(m, __shfl_xor_sync(0xffffffffu, m, 4));
            float e = __expf(logit - m);
            float sum = e;
            sum += __shfl_xor_sync(0xffffffffu, sum, 1);
            sum += __shfl_xor_sync(0xffffffffu, sum, 2);
            sum += __shfl_xor_sync(0xffffffffu, sum, 4);
            float a = e / sum + EPS_;
            if (it == 2) S2[k * (ML_NT + 4) + nl] = a;
            den += a;
            const float* vn = kn + 16;
#pragma unroll
            for (int s = 0; s < S_; s++) num[s] = fmaf(a, vn[s], num[s]);
        }

        // block reduction (R7-proven), into per-iteration global accumulators
        __syncthreads();
#pragma unroll
        for (int s = 0; s < S_; s++) S1[t * 17 + s] = num[s];
        S1[t * 17 + 16] = den;
        __syncthreads();
        {
            int k2 = t >> 4, s2 = t & 15;
            float v = 0.f;
#pragma unroll
            for (int gg = 0; gg < 16; gg++) v += S1[(gg * 8 + k2) * 17 + s2];
            atomicAdd(&g_num3[it * 4096 + b * 128 + k2 * 16 + s2], v);
            if (s2 == 0) {
                float dv = 0.f;
#pragma unroll
                for (int gg = 0; gg < 16; gg++) dv += S1[(gg * 8 + k2) * 17 + 16];
                atomicAdd(&g_den3[it * 256 + b * K_ + k2], dv);
            }
        }

        // ---------- grid barrier ----------
        grid_barrier((unsigned)ML_GRID * (unsigned)(it + 1));

        // ---------- read reduced num/den (L2, bypass L1) ----------
        float u_num = __ldcg(&g_num3[it * 4096 + b * 128 + t]);
        float u_den = __ldcg(&g_den3[it * 256 + b * K_ + (t >> 4)]);
        S1[t] = u_num / u_den;  // upd (red already fully consumed pre-barrier)

        if (it == 2) {
            // write normalized attn for this block's slice; then S2 is free
            if (t < K_) qlo[t] = 1.0f / __ldcg(&g_den3[it * 256 + b * K_ + t]);
            __syncthreads();
#pragma unroll 4
            for (int i = t; i < K_ * ML_NT; i += 128) {
                int kk = i >> 8, nn = i & (ML_NT - 1);
                out_attn[((long long)(b * K_ + kk)) * N_ + n0 + nn] =
                    S2[kk * (ML_NT + 4) + nn] * qlo[kk];
            }
        }
        __syncthreads();

        // ---------- update phase (R7-proven math; weights staged through S2) ----------
        // stage GRU weights
        for (int i = t; i < 768; i += 128) {
            S2[i] = __ldg(w_ih + i);
            S2[768 + i] = __ldg(w_hh + i);
        }
        __syncthreads();
#pragma unroll
        for (int i = 0; i < 3; i++) {
            int idx = t + i * 128;
            int kk = idx / 48, j = idx % 48;
            float gi = __ldg(b_ih + j), gh = __ldg(b_hh + j);
#pragma unroll
            for (int s = 0; s < S_; s++) {
                gi = fmaf(S1[kk * S_ + s], S2[j * S_ + s], gi);
                gh = fmaf(slb[kk * S_ + s], S2[768 + j * S_ + s], gh);
            }
            S1[384 + idx] = gi;
            S1[768 + idx] = gh;
        }
        __syncthreads();
        {
            int kk = t >> 4, s = t & 15;
            float ir = S1[384 + kk * 48 + s], hr = S1[768 + kk * 48 + s];
            float iz = S1[384 + kk * 48 + 16 + s], hz = S1[768 + kk * 48 + 16 + s];
            float inn = S1[384 + kk * 48 + 32 + s], hn = S1[768 + kk * 48 + 32 + s];
            float r = 1.f / (1.f + __expf(-(ir + hr)));
            float z = 1.f / (1.f + __expf(-(iz + hz)));
            float n = tanhf(inn + r * hn);
            float h = (1.f - z) * n + z * slb[t];
            S1[128 + t] = h;  // h_s
            float s1 = h, s2 = h * h;
#pragma unroll
            for (int o = 1; o <= 8; o <<= 1) {
                s1 += __shfl_xor_sync(0xffffffffu, s1, o);
                s2 += __shfl_xor_sync(0xffffffffu, s2, o);
            }
            float mu = s1 * (1.f / 16.f);
            float var = s2 * (1.f / 16.f) - mu * mu;
            float rs = rsqrtf(var + LN_EPS);
            S1[256 + t] = (h - mu) * rs * __ldg(ln_m_w + s) + __ldg(ln_m_b + s);  // y_s
        }
        __syncthreads();
        // stage ws1, MLP1
        for (int i = t; i < H_ * S_; i += 128) S2[i] = __ldg(w1 + i);
        __syncthreads();
#pragma unroll
        for (int i = 0; i < 8; i++) {
            int idx = t + i * 128;
            int kk = idx >> 7, hh = idx & 127;
            float acc = __ldg(b1 + hh);
#pragma unroll
            for (int s = 0; s < S_; s++) acc = fmaf(S1[256 + kk * S_ + s], S2[hh * S_ + s], acc);
            S1[1152 + idx] = fmaxf(acc, 0.f);  // hid
        }
        __syncthreads();
        // stage ws2, MLP2
        for (int i = t; i < S_ * H_; i += 128) S2[i] = __ldg(w2 + i);
        __syncthreads();
        float res;
        {
            int kk = t >> 4, s = t & 15;
            float acc = __ldg(b2 + s);
#pragma unroll 8
            for (int h = 0; h < H_; h++) acc = fmaf(S1[1152 + kk * H_ + h], S2[s * H_ + h], acc);
            res = S1[128 + t] + acc;
        }

        if (it == 2) {
            if (grp == 0) out_slots[b * 128 + t] = res;
        } else {
            __syncthreads();
            slb[t] = res;
            __syncthreads();
            // next q (proven body)
            if (t < K_) {
                float x[S_];
                float s = 0.f;
#pragma unroll
                for (int j = 0; j < S_; j++) {
                    x[j] = slb[t * S_ + j];
                    s += x[j];
                }
                float mu = s * (1.f / 16.f);
                float ss = 0.f;
#pragma unroll
                for (int j = 0; j < S_; j++) {
                    float d = x[j] - mu;
                    ss = fmaf(d, d, ss);
                }
                float rs = rsqrtf(ss * (1.f / 16.f) + LN_EPS);
                float y[S_];
#pragma unroll
                for (int j = 0; j < S_; j++)
                    y[j] = (x[j] - mu) * rs * __ldg(ln_s_w + j) + __ldg(ln_s_b + j);
#pragma unroll
                for (int tt = 0; tt < S_; tt++) {
                    float q = 0.f;
#pragma unroll
                    for (int j = 0; j < S_; j++) q = fmaf(y[j], __ldg(wq + tt * S_ + j), q);
                    qlo[t * S_ + tt] = q;
                }
            }
            __syncthreads();
        }
    }
}

// ---------------- launch: 3 graph nodes ----------------
extern "C" void kernel_launch(void* const* d_in, const int* in_sizes, int n_in,
                              void* d_out, int out_size) {
    const float* inputs = (const float*)d_in[0];
    const float* init_slots = (const float*)d_in[1];
    const float* ln_in_w = (const float*)d_in[2];
    const float* ln_in_b = (const float*)d_in[3];
    const float* ln_s_w = (const float*)d_in[4];
    const float* ln_s_b = (const float*)d_in[5];
    const float* ln_m_w = (const float*)d_in[6];
    const float* ln_m_b = (const float*)d_in[7];
    const float* wq = (const float*)d_in[8];
    const float* wk = (const float*)d_in[9];
    const float* wv = (const float*)d_in[10];
    const float* w_ih = (const float*)d_in[11];
    const float* w_hh = (const float*)d_in[12];
    const float* b_ih = (const float*)d_in[13];
    const float* b_hh = (const float*)d_in[14];
    const float* mlp_w1 = (const float*)d_in[15];
    const float* mlp_b1 = (const float*)d_in[16];
    const float* mlp_w2 = (const float*)d_in[17];
    const float* mlp_b2 = (const float*)d_in[18];

    float* out_slots = (float*)d_out;
    float* out_attn = out_slots + B_ * K_ * S_;

    const int lp_smem = LP_SMEM_FLOATS * sizeof(float);
    cudaFuncSetAttribute(lnproj_kernel, cudaFuncAttributeMaxDynamicSharedMemorySize, lp_smem);
    const int ml_smem = ML_SMEM_FLOATS * sizeof(float);
    cudaFuncSetAttribute(mainloop_kernel, cudaFuncAttributeMaxDynamicSharedMemorySize, ml_smem);

    prep_kernel<<<1, 1024>>>(wk, wv, ln_in_w, ln_in_b);
    lnproj_kernel<<<(B_ * N_) / LP_ROWS, LP_THREADS, lp_smem>>>(inputs);
    mainloop_kernel<<<ML_GRID, 128, ml_smem>>>(
        init_slots, ln_s_w, ln_s_b, wq, w_ih, w_hh, b_ih, b_hh,
        ln_m_w, ln_m_b, mlp_w1, mlp_b1, mlp_w2, mlp_b2, out_slots, out_attn);
}